// round 1
// baseline (speedup 1.0000x reference)
#include <cuda_runtime.h>

#define HID 4096
#define GATES (3*HID)
#define NVOCAB 256
#define ROWS_PER_BLOCK 8   // 8 warps, warp-per-row

// Scratch (allocation-free rule: __device__ globals)
__device__ float g_gi0[GATES];
__device__ float g_gh0[GATES];
__device__ float g_gh1[GATES];
__device__ float g_gi1[GATES];
__device__ float g_h0[HID];
__device__ float g_h1[HID];

__device__ __forceinline__ float sigmoidf_(float v) {
    return 1.0f / (1.0f + __expf(-v));
}

// ---------------------------------------------------------------------------
// Fused 3-matrix matvec: gi0 = W_ih0 @ emb[inp] + b_ih0
//                        gh0 = W_hh0 @ h[0]     + b_hh0
//                        gh1 = W_hh1 @ h[1]     + b_hh1
// Warp-per-row, x staged in shared. Grid = 3 * (12288/8) = 4608 blocks.
// ---------------------------------------------------------------------------
__global__ __launch_bounds__(256) void mv3_kernel(
    const int* __restrict__ inp, const float* __restrict__ hidden,
    const float* __restrict__ emb,
    const float* __restrict__ Wih0, const float* __restrict__ Whh0,
    const float* __restrict__ Whh1,
    const float* __restrict__ bih0, const float* __restrict__ bhh0,
    const float* __restrict__ bhh1)
{
    __shared__ float sx[HID];
    const int warp = threadIdx.x >> 5;
    const int lane = threadIdx.x & 31;

    const int blocks_per_seg = GATES / ROWS_PER_BLOCK;   // 1536
    const int seg    = blockIdx.x / blocks_per_seg;      // 0,1,2
    const int segblk = blockIdx.x % blocks_per_seg;

    const float* W; const float* b; const float* x; float* y;
    if (seg == 0)      { W = Wih0; b = bih0; x = emb + (size_t)inp[0] * HID; y = g_gi0; }
    else if (seg == 1) { W = Whh0; b = bhh0; x = hidden;                     y = g_gh0; }
    else               { W = Whh1; b = bhh1; x = hidden + HID;               y = g_gh1; }

    // Stage x into shared (16 KB)
    for (int i = threadIdx.x; i < HID / 4; i += blockDim.x)
        ((float4*)sx)[i] = ((const float4*)x)[i];
    __syncthreads();

    const int row = segblk * ROWS_PER_BLOCK + warp;
    const float4* __restrict__ w4 = (const float4*)(W + (size_t)row * HID);
    const float4* x4 = (const float4*)sx;

    float acc = 0.0f;
    #pragma unroll
    for (int i = 0; i < HID / 4 / 32; i++) {           // 32 iterations
        float4 a  = w4[lane + 32 * i];
        float4 xv = x4[lane + 32 * i];
        acc += a.x * xv.x + a.y * xv.y + a.z * xv.z + a.w * xv.w;
    }
    #pragma unroll
    for (int off = 16; off; off >>= 1)
        acc += __shfl_down_sync(0xffffffffu, acc, off);
    if (lane == 0) y[row] = acc + b[row];
}

// ---------------------------------------------------------------------------
// Single-matrix matvec: gi1 = W_ih1 @ g_h0 + b_ih1.  Grid = 1536 blocks.
// ---------------------------------------------------------------------------
__global__ __launch_bounds__(256) void mv1_kernel(
    const float* __restrict__ Wih1, const float* __restrict__ bih1)
{
    __shared__ float sx[HID];
    const int warp = threadIdx.x >> 5;
    const int lane = threadIdx.x & 31;

    for (int i = threadIdx.x; i < HID / 4; i += blockDim.x)
        ((float4*)sx)[i] = ((const float4*)g_h0)[i];
    __syncthreads();

    const int row = blockIdx.x * ROWS_PER_BLOCK + warp;
    const float4* __restrict__ w4 = (const float4*)(Wih1 + (size_t)row * HID);
    const float4* x4 = (const float4*)sx;

    float acc = 0.0f;
    #pragma unroll
    for (int i = 0; i < HID / 4 / 32; i++) {
        float4 a  = w4[lane + 32 * i];
        float4 xv = x4[lane + 32 * i];
        acc += a.x * xv.x + a.y * xv.y + a.z * xv.z + a.w * xv.w;
    }
    #pragma unroll
    for (int off = 16; off; off >>= 1)
        acc += __shfl_down_sync(0xffffffffu, acc, off);
    if (lane == 0) g_gi1[row] = acc + bih1[row];
}

// ---------------------------------------------------------------------------
// GRU gate math, layer 0: h0_new from gi0/gh0 + hidden[0]
// ---------------------------------------------------------------------------
__global__ void gate0_kernel(const float* __restrict__ hidden, float* __restrict__ out)
{
    int j = blockIdx.x * blockDim.x + threadIdx.x;
    if (j >= HID) return;
    float r = sigmoidf_(g_gi0[j]           + g_gh0[j]);
    float z = sigmoidf_(g_gi0[j + HID]     + g_gh0[j + HID]);
    float n = tanhf    (g_gi0[j + 2*HID] + r * g_gh0[j + 2*HID]);
    float h = (1.0f - z) * n + z * hidden[j];
    g_h0[j] = h;
    out[NVOCAB + j] = h;             // new_h[0]
}

// ---------------------------------------------------------------------------
// GRU gate math, layer 1: h1_new from gi1/gh1 + hidden[1]
// ---------------------------------------------------------------------------
__global__ void gate1_kernel(const float* __restrict__ hidden, float* __restrict__ out)
{
    int j = blockIdx.x * blockDim.x + threadIdx.x;
    if (j >= HID) return;
    float r = sigmoidf_(g_gi1[j]           + g_gh1[j]);
    float z = sigmoidf_(g_gi1[j + HID]     + g_gh1[j + HID]);
    float n = tanhf    (g_gi1[j + 2*HID] + r * g_gh1[j + 2*HID]);
    float h = (1.0f - z) * n + z * hidden[HID + j];
    g_h1[j] = h;
    out[NVOCAB + HID + j] = h;       // new_h[1]
}

// ---------------------------------------------------------------------------
// Decoder: out[0:256] = W_dec @ h1_new + b_dec.  Grid = 256/8 = 32 blocks.
// ---------------------------------------------------------------------------
__global__ __launch_bounds__(256) void dec_kernel(
    const float* __restrict__ Wdec, const float* __restrict__ bdec,
    float* __restrict__ out)
{
    __shared__ float sx[HID];
    const int warp = threadIdx.x >> 5;
    const int lane = threadIdx.x & 31;

    for (int i = threadIdx.x; i < HID / 4; i += blockDim.x)
        ((float4*)sx)[i] = ((const float4*)g_h1)[i];
    __syncthreads();

    const int row = blockIdx.x * ROWS_PER_BLOCK + warp;
    const float4* __restrict__ w4 = (const float4*)(Wdec + (size_t)row * HID);
    const float4* x4 = (const float4*)sx;

    float acc = 0.0f;
    #pragma unroll
    for (int i = 0; i < HID / 4 / 32; i++) {
        float4 a  = w4[lane + 32 * i];
        float4 xv = x4[lane + 32 * i];
        acc += a.x * xv.x + a.y * xv.y + a.z * xv.z + a.w * xv.w;
    }
    #pragma unroll
    for (int off = 16; off; off >>= 1)
        acc += __shfl_down_sync(0xffffffffu, acc, off);
    if (lane == 0) out[row] = acc + bdec[row];
}

// ---------------------------------------------------------------------------
// Inputs (metadata order):
// 0 inp(int32,1) 1 hidden(2*4096) 2 emb(256*4096)
// 3 W_ih0 4 W_hh0 5 b_ih0 6 b_hh0
// 7 W_ih1 8 W_hh1 9 b_ih1 10 b_hh1
// 11 W_dec 12 b_dec
// Output: [logits(256) | h0_new(4096) | h1_new(4096)]
// ---------------------------------------------------------------------------
extern "C" void kernel_launch(void* const* d_in, const int* in_sizes, int n_in,
                              void* d_out, int out_size)
{
    const int*   inp    = (const int*)  d_in[0];
    const float* hidden = (const float*)d_in[1];
    const float* emb    = (const float*)d_in[2];
    const float* Wih0   = (const float*)d_in[3];
    const float* Whh0   = (const float*)d_in[4];
    const float* bih0   = (const float*)d_in[5];
    const float* bhh0   = (const float*)d_in[6];
    const float* Wih1   = (const float*)d_in[7];
    const float* Whh1   = (const float*)d_in[8];
    const float* bih1   = (const float*)d_in[9];
    const float* bhh1   = (const float*)d_in[10];
    const float* Wdec   = (const float*)d_in[11];
    const float* bdec   = (const float*)d_in[12];
    float* out = (float*)d_out;

    const int mv_blocks = GATES / ROWS_PER_BLOCK;   // 1536 per matrix

    mv3_kernel<<<3 * mv_blocks, 256>>>(inp, hidden, emb, Wih0, Whh0, Whh1,
                                       bih0, bhh0, bhh1);
    gate0_kernel<<<HID / 256, 256>>>(hidden, out);
    mv1_kernel<<<mv_blocks, 256>>>(Wih1, bih1);
    gate1_kernel<<<HID / 256, 256>>>(hidden, out);
    dec_kernel<<<NVOCAB / ROWS_PER_BLOCK, 256>>>(Wdec, bdec, out);
}